// round 1
// baseline (speedup 1.0000x reference)
#include <cuda_runtime.h>
#include <math.h>

// Problem constants
#define BB 16
#define HH 384
#define WW 512
#define CC 3
#define HW (HH * WW)

// Per-batch precomputed transform: p = d * (N @ [u,v,1]) + T
// 12 floats per batch: N[9], T[3]
__device__ float g_M[BB][12];

__global__ void pose_kernel(const float* __restrict__ pose,
                            const float* __restrict__ K) {
    int b = threadIdx.x;
    if (b >= BB) return;

    // pose scaling per reference
    float tx = pose[b * 6 + 0] * 0.01f;
    float ty = pose[b * 6 + 1] * 0.01f;
    float tz = pose[b * 6 + 2] * 0.01f;
    float rx = pose[b * 6 + 3] * 0.001f;
    float ry = pose[b * 6 + 4] * 0.001f;
    float rz = pose[b * 6 + 5] * 0.001f;

    float cx = cosf(rx), sx = sinf(rx);
    float cy = cosf(ry), sy = sinf(ry);
    float cz = cosf(rz), sz = sinf(rz);

    // R = Rz @ Ry @ Rx (row-major 3x3)
    // Rz = [cz,-sz,0; sz,cz,0; 0,0,1]
    // Ry = [cy,0,sy; 0,1,0; -sy,0,cy]
    // Rx = [1,0,0; 0,cx,-sx; 0,sx,cx]
    float Rzy[9];
    // Rz @ Ry
    Rzy[0] = cz * cy;            Rzy[1] = -sz;  Rzy[2] = cz * sy;
    Rzy[3] = sz * cy;            Rzy[4] = cz;   Rzy[5] = sz * sy;
    Rzy[6] = -sy;                Rzy[7] = 0.f;  Rzy[8] = cy;
    float R[9];
    // (Rz@Ry) @ Rx
    R[0] = Rzy[0];
    R[1] = Rzy[1] * cx + Rzy[2] * sx;
    R[2] = -Rzy[1] * sx + Rzy[2] * cx;
    R[3] = Rzy[3];
    R[4] = Rzy[4] * cx + Rzy[5] * sx;
    R[5] = -Rzy[4] * sx + Rzy[5] * cx;
    R[6] = Rzy[6];
    R[7] = Rzy[7] * cx + Rzy[8] * sx;
    R[8] = -Rzy[7] * sx + Rzy[8] * cx;

    // Load intrinsics (3x3 row-major)
    float k00 = K[0], k01 = K[1], k02 = K[2];
    float k10 = K[3], k11 = K[4], k12 = K[5];
    float k20 = K[6], k21 = K[7], k22 = K[8];

    // General 3x3 inverse via adjugate (matches jnp.linalg.inv numerically)
    float c00 = k11 * k22 - k12 * k21;
    float c01 = k12 * k20 - k10 * k22;
    float c02 = k10 * k21 - k11 * k20;
    float det = k00 * c00 + k01 * c01 + k02 * c02;
    float id = 1.0f / det;
    float Ki[9];
    Ki[0] = c00 * id;
    Ki[1] = (k02 * k21 - k01 * k22) * id;
    Ki[2] = (k01 * k12 - k02 * k11) * id;
    Ki[3] = c01 * id;
    Ki[4] = (k00 * k22 - k02 * k20) * id;
    Ki[5] = (k02 * k10 - k00 * k12) * id;
    Ki[6] = c02 * id;
    Ki[7] = (k01 * k20 - k00 * k21) * id;
    Ki[8] = (k00 * k11 - k01 * k10) * id;

    // M33 = K @ R,  Mt = K @ t
    float M33[9], Mt[3];
    #pragma unroll
    for (int i = 0; i < 3; i++) {
        float a0 = (i == 0) ? k00 : (i == 1) ? k10 : k20;
        float a1 = (i == 0) ? k01 : (i == 1) ? k11 : k21;
        float a2 = (i == 0) ? k02 : (i == 1) ? k12 : k22;
        #pragma unroll
        for (int j = 0; j < 3; j++)
            M33[i * 3 + j] = a0 * R[0 * 3 + j] + a1 * R[1 * 3 + j] + a2 * R[2 * 3 + j];
        Mt[i] = a0 * tx + a1 * ty + a2 * tz;
    }

    // N = M33 @ Kinv  (so p = d * (N @ [u,v,1]) + Mt)
    #pragma unroll
    for (int i = 0; i < 3; i++) {
        #pragma unroll
        for (int j = 0; j < 3; j++) {
            g_M[b][i * 3 + j] = M33[i * 3 + 0] * Ki[0 * 3 + j]
                              + M33[i * 3 + 1] * Ki[1 * 3 + j]
                              + M33[i * 3 + 2] * Ki[2 * 3 + j];
        }
        g_M[b][9 + i] = Mt[i];
    }
}

__global__ void __launch_bounds__(256) warp_kernel(
    const float* __restrict__ src,
    const float* __restrict__ depth,
    float* __restrict__ out)
{
    int idx = blockIdx.x * blockDim.x + threadIdx.x;
    if (idx >= BB * HW) return;

    int b = idx / HW;
    int r = idx - b * HW;
    int v = r >> 9;          // WW = 512
    int u = r & (WW - 1);

    // Load per-batch matrix (L1/const-cached; same b across warp)
    const float* M = g_M[b];
    float n00 = __ldg(&M[0]), n01 = __ldg(&M[1]), n02 = __ldg(&M[2]);
    float n10 = __ldg(&M[3]), n11 = __ldg(&M[4]), n12 = __ldg(&M[5]);
    float n20 = __ldg(&M[6]), n21 = __ldg(&M[7]), n22 = __ldg(&M[8]);
    float t0  = __ldg(&M[9]), t1  = __ldg(&M[10]), t2 = __ldg(&M[11]);

    float d = __ldg(&depth[idx]);
    float uf = (float)u, vf = (float)v;

    float px = fmaf(d, fmaf(n00, uf, fmaf(n01, vf, n02)), t0);
    float py = fmaf(d, fmaf(n10, uf, fmaf(n11, vf, n12)), t1);
    float pz = fmaf(d, fmaf(n20, uf, fmaf(n21, vf, n22)), t2);

    float inv_z = 1.0f / (pz + 1e-10f);
    float xs = px * inv_z;
    float ys = py * inv_z;

    // Bilinear weights from unclamped floor coords (reference semantics)
    float x0f = floorf(xs), y0f = floorf(ys);
    float fx = xs - x0f, fy = ys - y0f;
    float gx = 1.0f - fx, gy = 1.0f - fy;
    float wa = gx * gy;   // (x0,y0)
    float wb = gx * fy;   // (x0,y1)
    float wc = fx * gy;   // (x1,y0)
    float wd = fx * fy;   // (x1,y1)

    // Clamp on float, then cast (reference semantics)
    float x1f = x0f + 1.0f, y1f = y0f + 1.0f;
    int x0 = (int)fminf(fmaxf(x0f, 0.0f), (float)(WW - 1));
    int x1 = (int)fminf(fmaxf(x1f, 0.0f), (float)(WW - 1));
    int y0 = (int)fminf(fmaxf(y0f, 0.0f), (float)(HH - 1));
    int y1 = (int)fminf(fmaxf(y1f, 0.0f), (float)(HH - 1));

    const float* base = src + (size_t)b * HW * CC;
    const float* pa = base + (y0 * WW + x0) * CC;
    const float* pb = base + (y1 * WW + x0) * CC;
    const float* pc = base + (y0 * WW + x1) * CC;
    const float* pd = base + (y1 * WW + x1) * CC;

    float a0 = __ldg(&pa[0]), a1 = __ldg(&pa[1]), a2 = __ldg(&pa[2]);
    float b0 = __ldg(&pb[0]), b1 = __ldg(&pb[1]), b2 = __ldg(&pb[2]);
    float c0 = __ldg(&pc[0]), c1 = __ldg(&pc[1]), c2 = __ldg(&pc[2]);
    float d0 = __ldg(&pd[0]), d1 = __ldg(&pd[1]), d2 = __ldg(&pd[2]);

    float o0 = fmaf(wa, a0, fmaf(wb, b0, fmaf(wc, c0, wd * d0)));
    float o1 = fmaf(wa, a1, fmaf(wb, b1, fmaf(wc, c1, wd * d1)));
    float o2 = fmaf(wa, a2, fmaf(wb, b2, fmaf(wc, c2, wd * d2)));

    float* op = out + (size_t)idx * CC;
    op[0] = o0;
    op[1] = o1;
    op[2] = o2;
}

extern "C" void kernel_launch(void* const* d_in, const int* in_sizes, int n_in,
                              void* d_out, int out_size) {
    const float* src   = (const float*)d_in[0];   // [B,H,W,C]
    const float* depth = (const float*)d_in[1];   // [B,H,W]
    const float* pose  = (const float*)d_in[2];   // [B,6]
    const float* K     = (const float*)d_in[3];   // [3,3]
    float* out = (float*)d_out;

    pose_kernel<<<1, 32>>>(pose, K);

    int total = BB * HW;
    int threads = 256;
    int blocks = (total + threads - 1) / threads;
    warp_kernel<<<blocks, threads>>>(src, depth, out);
}